// round 16
// baseline (speedup 1.0000x reference)
#include <cuda_runtime.h>
#include <cuda_fp16.h>
#include <math.h>

#define NPIX 65536
#define TWO_PI 6.283185307179586f
#define LSTRIDE 257                 // per-line transpose-buffer stride (float2)
#define SWZ(r, c) ((r) * 16 + ((c) ^ (r)))   // XOR-swizzled 16x16 transpose slot

// ---------------- scratch (device globals) ------------------------------------
__device__ float   g_fR[9 * NPIX];    // filter hats REAL part (psi 0..7, phi 8)
__device__ float2  g_fB[9 * NPIX];    // filter row-FFT temp; later Sphi (8 img)
__device__ float2  g_xT[8 * NPIX];    // x row-FFT
__device__ float2  g_S2[64 * NPIX];   // U1 row-fwd-FFT (U1h rows)
__device__ float2  g_S[64 * NPIX];    // U1 mid; later U1h-col buffer (32 MB)
__device__ __half2 g_Sh[512 * NPIX];  // U2 mid (half2, 128 MB); head doubles as Xh scratch
__device__ float   g_gs[8];
__device__ float2  g_ws[8];

__device__ __forceinline__ float2 cmulf(float2 a, float2 b) {
  return make_float2(a.x * b.x - a.y * b.y, a.x * b.y + a.y * b.x);
}
__device__ __forceinline__ float2 cadd(float2 a, float2 b){ return make_float2(a.x+b.x, a.y+b.y); }
__device__ __forceinline__ float2 csub(float2 a, float2 b){ return make_float2(a.x-b.x, a.y-b.y); }

template<int SGN>
__device__ __forceinline__ void dft4(float2& x0, float2& x1, float2& x2, float2& x3){
  float2 t0 = cadd(x0,x2), t1 = csub(x0,x2);
  float2 t2 = cadd(x1,x3), t3 = csub(x1,x3);
  float2 it3 = make_float2(-(float)SGN * t3.y, (float)SGN * t3.x);
  x0 = cadd(t0,t2);
  x1 = cadd(t1,it3);
  x2 = csub(t0,t2);
  x3 = csub(t1,it3);
}

// 16-pt DFT in registers. Input v[n] natural; output y[k0+4k1] at v[4k0+k1].
#define PERM(k) ((((k)&3)<<2)|((k)>>2))
template<int SGN>
__device__ __forceinline__ void fft16(float2 v[16]){
  const float C[10] = {1.f, 0.9238795325f, 0.7071067812f, 0.3826834324f, 0.f,
                       -0.3826834324f, -0.7071067812f, -0.9238795325f, -1.f, -0.9238795325f};
  const float S[10] = {0.f, 0.3826834324f, 0.7071067812f, 0.9238795325f, 1.f,
                       0.9238795325f, 0.7071067812f, 0.3826834324f, 0.f, -0.3826834324f};
#pragma unroll
  for (int n0 = 0; n0 < 4; ++n0)
    dft4<SGN>(v[n0], v[4+n0], v[8+n0], v[12+n0]);
#pragma unroll
  for (int n0 = 1; n0 < 4; ++n0)
#pragma unroll
    for (int k0 = 1; k0 < 4; ++k0) {
      int m = n0 * k0;
      float2 w = make_float2(C[m], (float)SGN * S[m]);
      v[n0 + 4*k0] = cmulf(v[n0 + 4*k0], w);
    }
#pragma unroll
  for (int k0 = 0; k0 < 4; ++k0)
    dft4<SGN>(v[4*k0+0], v[4*k0+1], v[4*k0+2], v[4*k0+3]);
}

// 256-pt FFT. Thread t (of 16 per line) holds x[16*n1+t] in v[n1].
// On exit: X[t+16*k2] is in v[PERM(k2)]. Twiddles via 4 parallel chains.
template<int SGN, bool BSYNC>
__device__ __forceinline__ void fft256_reg(float2 v[16], float2* sm, int t){
  fft16<SGN>(v);
  if (BSYNC) __syncthreads(); else __syncwarp();   // guard buffer reuse
  float ang = (float)SGN * TWO_PI * (float)t * (1.f / 256.f);
  float sn, cs; __sincosf(ang, &sn, &cs);
  float2 w1 = make_float2(cs, sn);
  float2 w2 = cmulf(w1, w1);
  float2 w4 = cmulf(w2, w2);
  float2 cw0 = make_float2(1.f, 0.f);
  float2 cw1 = w1;
  float2 cw2 = w2;
  float2 cw3 = cmulf(w2, w1);
#pragma unroll
  for (int q = 0; q < 4; ++q) {
    sm[SWZ(4*q + 0, t)] = cmulf(v[PERM(4*q + 0)], cw0);
    sm[SWZ(4*q + 1, t)] = cmulf(v[PERM(4*q + 1)], cw1);
    sm[SWZ(4*q + 2, t)] = cmulf(v[PERM(4*q + 2)], cw2);
    sm[SWZ(4*q + 3, t)] = cmulf(v[PERM(4*q + 3)], cw3);
    if (q < 3) {
      cw0 = cmulf(cw0, w4);
      cw1 = cmulf(cw1, w4);
      cw2 = cmulf(cw2, w4);
      cw3 = cmulf(cw3, w4);
    }
  }
  if (BSYNC) __syncthreads(); else __syncwarp();
#pragma unroll
  for (int n2 = 0; n2 < 16; ++n2) v[n2] = sm[SWZ(t, n2)];  // element (t, n2)
  fft16<SGN>(v);
}

// ---------------- merged head kernels ------------------------------------------
// Blocks [0,8): filter sums (reduction in SM scratch). Blocks [8,136): x row FFT.
__global__ void __launch_bounds__(256, 4) k_sums_xrow(
    const float* theta, const float* xis, const float* sigmas, const float* slants,
    const float* x, float2* xT) {
  __shared__ float2 SM[16 * LSTRIDE];
  if (blockIdx.x < 8) {
    int f = blockIdx.x;
    float th = theta[f], xi = xis[f], sg = sigmas[f], sl = slants[f];
    float c = cosf(th), s = sinf(th);
    float a0 = sl / sg, a1 = 1.f / sg;
    float gsum = 0.f, wr = 0.f, wi = 0.f;
    for (int p = threadIdx.x; p < NPIX; p += 256) {
      float gm = (float)((p >> 8) - 128);
      float gn = (float)((p & 255) - 128);
      float u = c * gm + s * gn;
      float vv = -s * gm + c * gn;
      float g = expf(-0.5f * (a0 * a0 * u * u + a1 * a1 * vv * vv));
      float sn, cn;
      sincosf(xi * u, &sn, &cn);
      gsum += g; wr += cn * g; wi += sn * g;
    }
    float* r0 = (float*)SM;
    float* r1 = r0 + 256;
    float* r2 = r1 + 256;
    int tid = threadIdx.x;
    r0[tid] = gsum; r1[tid] = wr; r2[tid] = wi;
    __syncthreads();
    for (int s2 = 128; s2 > 0; s2 >>= 1) {
      if (tid < s2) { r0[tid] += r0[tid + s2]; r1[tid] += r1[tid + s2]; r2[tid] += r2[tid + s2]; }
      __syncthreads();
    }
    if (tid == 0) { g_gs[f] = r0[0]; g_ws[f] = make_float2(r1[0], r2[0]); }
  } else {
    int t = threadIdx.x & 15, line = threadIdx.x >> 4;
    size_t base = ((size_t)(blockIdx.x - 8) * 16 + line) << 8;
    float2 v[16];
#pragma unroll
    for (int n1 = 0; n1 < 16; ++n1) v[n1] = make_float2(x[base + 16*n1 + t], 0.f);
    fft256_reg<-1, false>(v, SM + line * LSTRIDE, t);
#pragma unroll
    for (int k2 = 0; k2 < 16; ++k2)
      xT[base + t + 16*k2] = v[PERM(k2)];
  }
}

// Blocks [0,144): build spatial filters (ifftshift baked in, PRESCALED 1/65536)
// + forward row FFT -> fB. Blocks [144,272): x forward column FFT -> Xh.
__global__ void __launch_bounds__(256, 4) k_fbuild_xcol(
    const float* theta, const float* xis, const float* sigmas, const float* slants,
    float2* fB, const float2* xT, float2* Xh) {
  __shared__ float2 SM[16 * LSTRIDE];
  if (blockIdx.x < 144) {
    const float FSCALE = 1.f / 65536.f;
    int t = threadIdx.x & 15, line = threadIdx.x >> 4;
    int f = blockIdx.x >> 4;
    int row = ((blockIdx.x & 15) << 4) + line;
    float gm = (row < 128) ? (float)row : (float)(row - 256);
    float2 v[16];
    if (f < 8) {
      float th = theta[f], xi = xis[f], sg = sigmas[f], sl = slants[f];
      float c = cosf(th), s = sinf(th);
      float a0 = sl / sg, a1 = 1.f / sg;
      float Kr = g_ws[f].x / g_gs[f];
      float Ki = g_ws[f].y / g_gs[f];
      float invn = sl / (TWO_PI * sg * sg) * FSCALE;
#pragma unroll
      for (int n1 = 0; n1 < 16; ++n1) {
        int jd = 16 * n1 + t;
        float gn = (jd < 128) ? (float)jd : (float)(jd - 256);
        float u = c * gm + s * gn;
        float vv = -s * gm + c * gn;
        float g = expf(-0.5f * (a0 * a0 * u * u + a1 * a1 * vv * vv));
        float sn, cn;
        sincosf(xi * u, &sn, &cn);
        v[n1] = make_float2((cn - Kr) * g * invn, (sn - Ki) * g * invn);
      }
    } else {
      const float sp = 3.2f;
      float norm = FSCALE / (TWO_PI * sp * sp);
#pragma unroll
      for (int n1 = 0; n1 < 16; ++n1) {
        int jd = 16 * n1 + t;
        float gn = (jd < 128) ? (float)jd : (float)(jd - 256);
        float g = expf(-0.5f * (gm * gm + gn * gn) / (sp * sp));
        v[n1] = make_float2(g * norm, 0.f);
      }
    }
    fft256_reg<-1, false>(v, SM + line * LSTRIDE, t);
    size_t base = ((size_t)(f * 256 + row)) << 8;
#pragma unroll
    for (int k2 = 0; k2 < 16; ++k2)
      fB[base + t + 16*k2] = v[PERM(k2)];
  } else {
    int c = threadIdx.x & 15, t = threadIdx.x >> 4;
    int bb = blockIdx.x - 144;
    int img = bb >> 4;
    size_t base = ((size_t)img << 16) + ((bb & 15) << 4) + c;
    float2 v[16];
#pragma unroll
    for (int n1 = 0; n1 < 16; ++n1)
      v[n1] = xT[base + ((size_t)(16*n1 + t) << 8)];
    fft256_reg<-1, true>(v, SM + c * LSTRIDE, t);
#pragma unroll
    for (int k2 = 0; k2 < 16; ++k2)
      Xh[base + ((size_t)(t + 16*k2) << 8)] = v[PERM(k2)];
  }
}

// Filter column FFT, writing only the REAL part (filter hats are real up to
// fp noise: Morlet = real even Gaussians in frequency).
__global__ void __launch_bounds__(256, 4) k_fcolreal(const float2* in, float* out) {
  __shared__ float2 SM[16 * LSTRIDE];
  int c = threadIdx.x & 15, t = threadIdx.x >> 4;
  int img = blockIdx.x >> 4;
  size_t base = ((size_t)img << 16) + ((blockIdx.x & 15) << 4) + c;
  float2 v[16];
#pragma unroll
  for (int n1 = 0; n1 < 16; ++n1)
    v[n1] = in[base + ((size_t)(16*n1 + t) << 8)];
  fft256_reg<-1, true>(v, SM + c * LSTRIDE, t);
#pragma unroll
  for (int k2 = 0; k2 < 16; ++k2)
    out[base + ((size_t)(t + 16*k2) << 8)] = v[PERM(k2)].x;
}

// Forward column FFT (generic, depth-1). Used for S2 -> U1h-col (64 img).
__global__ void __launch_bounds__(256, 4) k_colfwd(const float2* in, float2* out) {
  __shared__ float2 SM[16 * LSTRIDE];
  int c = threadIdx.x & 15, t = threadIdx.x >> 4;
  int img = blockIdx.x >> 4;
  size_t base = ((size_t)img << 16) + ((blockIdx.x & 15) << 4) + c;
  float2 v[16];
#pragma unroll
  for (int n1 = 0; n1 < 16; ++n1)
    v[n1] = in[base + ((size_t)(16*n1 + t) << 8)];
  fft256_reg<-1, true>(v, SM + c * LSTRIDE, t);
#pragma unroll
  for (int k2 = 0; k2 < 16; ++k2)
    out[base + ((size_t)(t + 16*k2) << 8)] = v[PERM(k2)];
}

// X-stage: real-filter mul + inverse col FFT, depth-1 per block.
// grid = 8 img * 9 filters * 16 grps = 1152 blocks.
__global__ void __launch_bounds__(256, 4) k_icolmul9(const float2* Xh, const float* filt,
                                                     float2* Spsi, float2* Sphi) {
  __shared__ float2 SM[16 * LSTRIDE];
  int c = threadIdx.x & 15, t = threadIdx.x >> 4;
  int bid = blockIdx.x;
  int img = bid / 144;
  int rem = bid - img * 144;
  int f = rem >> 4;
  int grp = rem & 15;
  size_t cb = ((size_t)grp << 4) + c;
  const float2* src = Xh + ((size_t)img << 16);
  const float* ff = filt + ((size_t)f << 16);
  float2 v[16];
#pragma unroll
  for (int n1 = 0; n1 < 16; ++n1) {
    size_t a = cb + ((size_t)(16*n1 + t) << 8);
    float g = ff[a];
    float2 xh = src[a];
    v[n1] = make_float2(xh.x * g, xh.y * g);
  }
  fft256_reg<1, true>(v, SM + c * LSTRIDE, t);
  float2* dst = (f == 8) ? (Sphi + ((size_t)img << 16))
                         : (Spsi + ((size_t)(img * 8 + f) << 16));
#pragma unroll
  for (int k2 = 0; k2 < 16; ++k2)
    dst[cb + ((size_t)(t + 16*k2) << 8)] = v[PERM(k2)];
}

// U2-stage: real-filter mul + inverse col FFT, depth-1 per block, half2 out.
// grid = 64 img * 8 filters * 16 grps = 8192 blocks.
__global__ void __launch_bounds__(256, 4) k_icolmul8(const float2* Uh, const float* filt,
                                                     __half2* Smid) {
  __shared__ float2 SM[16 * LSTRIDE];
  int c = threadIdx.x & 15, t = threadIdx.x >> 4;
  int bid = blockIdx.x;
  int img = bid >> 7;         // /128
  int rem = bid & 127;
  int f = rem >> 4;
  int grp = rem & 15;
  size_t cb = ((size_t)grp << 4) + c;
  const float2* src = Uh + ((size_t)img << 16);
  const float* ff = filt + ((size_t)f << 16);
  float2 v[16];
#pragma unroll
  for (int n1 = 0; n1 < 16; ++n1) {
    size_t a = cb + ((size_t)(16*n1 + t) << 8);
    float g = ff[a];
    float2 xh = src[a];
    v[n1] = make_float2(xh.x * g, xh.y * g);
  }
  fft256_reg<1, true>(v, SM + c * LSTRIDE, t);
  __half2* dst = Smid + ((size_t)(img * 8 + f) << 16);
#pragma unroll
  for (int k2 = 0; k2 < 16; ++k2) {
    float2 y = v[PERM(k2)];
    dst[cb + ((size_t)(t + 16*k2) << 8)] = __floats2half2_rn(y.x, y.y);
  }
}

// MERGED kernel: blocks [0,1024) = U1 rows (inv row FFT of S, abs -> out
// channel, fwd row FFT -> S2); blocks [1024,1152) = S0 rows (real -> out).
__global__ void __launch_bounds__(256, 4) k_U1S0rows(const float2* mid, float* out,
                                                     float2* S2, const float2* Sphi) {
  __shared__ float2 SM[16 * LSTRIDE];
  int t = threadIdx.x & 15, line = threadIdx.x >> 4;
  if (blockIdx.x < 1024) {
    size_t gl = (size_t)blockIdx.x * 16 + line;
    int o = (int)(gl >> 8);
    int row = (int)(gl & 255);
    size_t base = gl << 8;
    float2 v[16];
#pragma unroll
    for (int n1 = 0; n1 < 16; ++n1) v[n1] = mid[base + 16*n1 + t];
    fft256_reg<1, false>(v, SM + line * LSTRIDE, t);

    int f = o & 7, bc = o >> 3;
    int b = bc >> 1, ch = (bc & 1) * 73 + 1 + f;
    size_t obase = (((size_t)(b * 146 + ch)) << 16) + ((size_t)row << 8);
    float2 a[16];
#pragma unroll
    for (int k = 0; k < 16; ++k) {
      float2 y = v[PERM(k)];
      float m = sqrtf(y.x * y.x + y.y * y.y);
      out[obase + t + 16*k] = m;
      a[k] = make_float2(m, 0.f);   // value at index 16k+t -> input slot k
    }
    fft256_reg<-1, false>(a, SM + line * LSTRIDE, t);
#pragma unroll
    for (int k2 = 0; k2 < 16; ++k2)
      S2[base + t + 16*k2] = a[PERM(k2)];
  } else {
    size_t gl = (size_t)(blockIdx.x - 1024) * 16 + line;
    int o = (int)(gl >> 8);
    int row = (int)(gl & 255);
    size_t base = gl << 8;
    float2 v[16];
#pragma unroll
    for (int n1 = 0; n1 < 16; ++n1) v[n1] = Sphi[base + 16*n1 + t];
    fft256_reg<1, false>(v, SM + line * LSTRIDE, t);
    int b = o >> 1, ch = (o & 1) * 73;
    size_t obase = (((size_t)(b * 146 + ch)) << 16) + ((size_t)row << 8);
#pragma unroll
    for (int k2 = 0; k2 < 16; ++k2)
      out[obase + t + 16*k2] = v[PERM(k2)].x;
  }
}

// U2 final inverse row pass: abs -> out channel.
__global__ void __launch_bounds__(256, 4) k_irow_U2(const __half2* mid, float* out) {
  __shared__ float2 SM[16 * LSTRIDE];
  int t = threadIdx.x & 15, line = threadIdx.x >> 4;
  size_t gl = (size_t)blockIdx.x * 16 + line;
  int o = (int)(gl >> 8);
  int row = (int)(gl & 255);
  size_t base = gl << 8;
  float2 v[16];
#pragma unroll
  for (int n1 = 0; n1 < 16; ++n1) v[n1] = __half22float2(mid[base + 16*n1 + t]);
  fft256_reg<1, false>(v, SM + line * LSTRIDE, t);

  int f2 = o & 7, tt = o >> 3;
  int f1 = tt & 7, bc = tt >> 3;
  int b = bc >> 1, ch = (bc & 1) * 73 + 9 + f1 * 8 + f2;
  size_t obase = (((size_t)(b * 146 + ch)) << 16) + ((size_t)row << 8);
#pragma unroll
  for (int k2 = 0; k2 < 16; ++k2) {
    float2 y = v[PERM(k2)];
    out[obase + t + 16*k2] = sqrtf(y.x * y.x + y.y * y.y);
  }
}

// ---------------- launch -------------------------------------------------------
extern "C" void kernel_launch(void* const* d_in, const int* in_sizes, int n_in,
                              void* d_out, int out_size) {
  (void)in_sizes; (void)n_in; (void)out_size;
  const float* x = (const float*)d_in[0];
  const float* theta = (const float*)d_in[1];
  const float* xis = (const float*)d_in[2];
  const float* sigmas = (const float*)d_in[3];
  const float* slants = (const float*)d_in[4];
  float* out = (float*)d_out;

  void* p;
  cudaGetSymbolAddress(&p, g_fR); float*  fR = (float*)p;
  cudaGetSymbolAddress(&p, g_fB); float2* fB = (float2*)p;
  cudaGetSymbolAddress(&p, g_xT); float2* xT = (float2*)p;
  cudaGetSymbolAddress(&p, g_S2); float2* S2 = (float2*)p;
  cudaGetSymbolAddress(&p, g_S);  float2* S  = (float2*)p;   // U1 mid; later U1h-col
  cudaGetSymbolAddress(&p, g_Sh); __half2* Sh = (__half2*)p;
  float2* Xh = (float2*)p;   // head of g_Sh doubles as Xhat scratch (4 MB; consumed before icolmul8)

  // Merged: filter sums (8 blks) || x row FFT (128 blks).
  k_sums_xrow<<<8 + 128, 256>>>(theta, xis, sigmas, slants, x, xT);

  // Merged: filter spatial-build + row FFT (144) || x col FFT (128).
  k_fbuild_xcol<<<144 + 128, 256>>>(theta, xis, sigmas, slants, fB, xT, Xh);

  // Filter col FFT, real part -> fR.
  k_fcolreal<<<9 * 16, 256>>>(fB, fR);

  // X-stage: 9x (real-mul + inv col FFT), depth-1.
  k_icolmul9<<<8 * 144, 256>>>(Xh, fR, S, fB);

  // Merged: U1 rows (abs -> out, fwd row FFT -> S2) || S0 rows (real -> out).
  k_U1S0rows<<<1024 + 128, 256>>>(S, out, S2, fB);

  // U2 stage, depth-1: fwd col FFT of S2 -> U1h-col (reuses g_S), then
  // 8x (real-mul + inv col FFT) -> half2 mid.
  k_colfwd<<<64 * 16, 256>>>(S2, S);
  k_icolmul8<<<64 * 128, 256>>>(S, fR, Sh);

  // U2 rows: abs -> out
  k_irow_U2<<<512 * 16, 256>>>(Sh, out);
}

// round 17
// speedup vs baseline: 1.0562x; 1.0562x over previous
#include <cuda_runtime.h>
#include <cuda_fp16.h>
#include <math.h>

#define NPIX 65536
#define TWO_PI 6.283185307179586f
#define LSTRIDE 257                 // per-line transpose-buffer stride (float2)
#define SWZ(r, c) ((r) * 16 + ((c) ^ (r)))   // XOR-swizzled 16x16 transpose slot

// ---------------- scratch (device globals) ------------------------------------
__device__ float   g_fR[9 * NPIX];    // filter hats REAL part (psi 0..7, phi 8)
__device__ float2  g_fB[9 * NPIX];    // filter row-FFT temp; later Sphi (8 img)
__device__ float2  g_xT[8 * NPIX];    // x row-FFT
__device__ float2  g_S2[64 * NPIX];   // U1 row-fwd-FFT (U1h rows)
__device__ float2  g_S[64 * NPIX];    // U1 mid (col-inv), float2
__device__ __half2 g_Sh[512 * NPIX];  // U2 mid (half2, 128 MB); head doubles as Xh scratch
__device__ float   g_gs[8];
__device__ float2  g_ws[8];

__device__ __forceinline__ float2 cmulf(float2 a, float2 b) {
  return make_float2(a.x * b.x - a.y * b.y, a.x * b.y + a.y * b.x);
}
__device__ __forceinline__ float2 cadd(float2 a, float2 b){ return make_float2(a.x+b.x, a.y+b.y); }
__device__ __forceinline__ float2 csub(float2 a, float2 b){ return make_float2(a.x-b.x, a.y-b.y); }

template<int SGN>
__device__ __forceinline__ void dft4(float2& x0, float2& x1, float2& x2, float2& x3){
  float2 t0 = cadd(x0,x2), t1 = csub(x0,x2);
  float2 t2 = cadd(x1,x3), t3 = csub(x1,x3);
  float2 it3 = make_float2(-(float)SGN * t3.y, (float)SGN * t3.x);
  x0 = cadd(t0,t2);
  x1 = cadd(t1,it3);
  x2 = csub(t0,t2);
  x3 = csub(t1,it3);
}

// 16-pt DFT in registers. Input v[n] natural; output y[k0+4k1] at v[4k0+k1].
#define PERM(k) ((((k)&3)<<2)|((k)>>2))
template<int SGN>
__device__ __forceinline__ void fft16(float2 v[16]){
  const float C[10] = {1.f, 0.9238795325f, 0.7071067812f, 0.3826834324f, 0.f,
                       -0.3826834324f, -0.7071067812f, -0.9238795325f, -1.f, -0.9238795325f};
  const float S[10] = {0.f, 0.3826834324f, 0.7071067812f, 0.9238795325f, 1.f,
                       0.9238795325f, 0.7071067812f, 0.3826834324f, 0.f, -0.3826834324f};
#pragma unroll
  for (int n0 = 0; n0 < 4; ++n0)
    dft4<SGN>(v[n0], v[4+n0], v[8+n0], v[12+n0]);
#pragma unroll
  for (int n0 = 1; n0 < 4; ++n0)
#pragma unroll
    for (int k0 = 1; k0 < 4; ++k0) {
      int m = n0 * k0;
      float2 w = make_float2(C[m], (float)SGN * S[m]);
      v[n0 + 4*k0] = cmulf(v[n0 + 4*k0], w);
    }
#pragma unroll
  for (int k0 = 0; k0 < 4; ++k0)
    dft4<SGN>(v[4*k0+0], v[4*k0+1], v[4*k0+2], v[4*k0+3]);
}

// 256-pt FFT. Thread t (of 16 per line) holds x[16*n1+t] in v[n1].
// On exit: X[t+16*k2] is in v[PERM(k2)]. Twiddles via 4 parallel chains.
template<int SGN, bool BSYNC>
__device__ __forceinline__ void fft256_reg(float2 v[16], float2* sm, int t){
  fft16<SGN>(v);
  if (BSYNC) __syncthreads(); else __syncwarp();   // guard buffer reuse
  float ang = (float)SGN * TWO_PI * (float)t * (1.f / 256.f);
  float sn, cs; __sincosf(ang, &sn, &cs);
  float2 w1 = make_float2(cs, sn);
  float2 w2 = cmulf(w1, w1);
  float2 w4 = cmulf(w2, w2);
  float2 cw0 = make_float2(1.f, 0.f);
  float2 cw1 = w1;
  float2 cw2 = w2;
  float2 cw3 = cmulf(w2, w1);
#pragma unroll
  for (int q = 0; q < 4; ++q) {
    sm[SWZ(4*q + 0, t)] = cmulf(v[PERM(4*q + 0)], cw0);
    sm[SWZ(4*q + 1, t)] = cmulf(v[PERM(4*q + 1)], cw1);
    sm[SWZ(4*q + 2, t)] = cmulf(v[PERM(4*q + 2)], cw2);
    sm[SWZ(4*q + 3, t)] = cmulf(v[PERM(4*q + 3)], cw3);
    if (q < 3) {
      cw0 = cmulf(cw0, w4);
      cw1 = cmulf(cw1, w4);
      cw2 = cmulf(cw2, w4);
      cw3 = cmulf(cw3, w4);
    }
  }
  if (BSYNC) __syncthreads(); else __syncwarp();
#pragma unroll
  for (int n2 = 0; n2 < 16; ++n2) v[n2] = sm[SWZ(t, n2)];  // element (t, n2)
  fft16<SGN>(v);
}

// ---------------- merged head kernels ------------------------------------------
// Blocks [0,8): filter sums (reduction in SM scratch). Blocks [8,136): x row FFT.
__global__ void __launch_bounds__(256, 4) k_sums_xrow(
    const float* theta, const float* xis, const float* sigmas, const float* slants,
    const float* x, float2* xT) {
  __shared__ float2 SM[16 * LSTRIDE];
  if (blockIdx.x < 8) {
    int f = blockIdx.x;
    float th = theta[f], xi = xis[f], sg = sigmas[f], sl = slants[f];
    float c = cosf(th), s = sinf(th);
    float a0 = sl / sg, a1 = 1.f / sg;
    float gsum = 0.f, wr = 0.f, wi = 0.f;
    for (int p = threadIdx.x; p < NPIX; p += 256) {
      float gm = (float)((p >> 8) - 128);
      float gn = (float)((p & 255) - 128);
      float u = c * gm + s * gn;
      float vv = -s * gm + c * gn;
      float g = expf(-0.5f * (a0 * a0 * u * u + a1 * a1 * vv * vv));
      float sn, cn;
      sincosf(xi * u, &sn, &cn);
      gsum += g; wr += cn * g; wi += sn * g;
    }
    float* r0 = (float*)SM;
    float* r1 = r0 + 256;
    float* r2 = r1 + 256;
    int tid = threadIdx.x;
    r0[tid] = gsum; r1[tid] = wr; r2[tid] = wi;
    __syncthreads();
    for (int s2 = 128; s2 > 0; s2 >>= 1) {
      if (tid < s2) { r0[tid] += r0[tid + s2]; r1[tid] += r1[tid + s2]; r2[tid] += r2[tid + s2]; }
      __syncthreads();
    }
    if (tid == 0) { g_gs[f] = r0[0]; g_ws[f] = make_float2(r1[0], r2[0]); }
  } else {
    int t = threadIdx.x & 15, line = threadIdx.x >> 4;
    size_t base = ((size_t)(blockIdx.x - 8) * 16 + line) << 8;
    float2 v[16];
#pragma unroll
    for (int n1 = 0; n1 < 16; ++n1) v[n1] = make_float2(x[base + 16*n1 + t], 0.f);
    fft256_reg<-1, false>(v, SM + line * LSTRIDE, t);
#pragma unroll
    for (int k2 = 0; k2 < 16; ++k2)
      xT[base + t + 16*k2] = v[PERM(k2)];
  }
}

// Blocks [0,144): build spatial filters (ifftshift baked in, PRESCALED 1/65536)
// + forward row FFT -> fB. Blocks [144,272): x forward column FFT -> Xh.
__global__ void __launch_bounds__(256, 4) k_fbuild_xcol(
    const float* theta, const float* xis, const float* sigmas, const float* slants,
    float2* fB, const float2* xT, float2* Xh) {
  __shared__ float2 SM[16 * LSTRIDE];
  if (blockIdx.x < 144) {
    const float FSCALE = 1.f / 65536.f;
    int t = threadIdx.x & 15, line = threadIdx.x >> 4;
    int f = blockIdx.x >> 4;
    int row = ((blockIdx.x & 15) << 4) + line;
    float gm = (row < 128) ? (float)row : (float)(row - 256);
    float2 v[16];
    if (f < 8) {
      float th = theta[f], xi = xis[f], sg = sigmas[f], sl = slants[f];
      float c = cosf(th), s = sinf(th);
      float a0 = sl / sg, a1 = 1.f / sg;
      float Kr = g_ws[f].x / g_gs[f];
      float Ki = g_ws[f].y / g_gs[f];
      float invn = sl / (TWO_PI * sg * sg) * FSCALE;
#pragma unroll
      for (int n1 = 0; n1 < 16; ++n1) {
        int jd = 16 * n1 + t;
        float gn = (jd < 128) ? (float)jd : (float)(jd - 256);
        float u = c * gm + s * gn;
        float vv = -s * gm + c * gn;
        float g = expf(-0.5f * (a0 * a0 * u * u + a1 * a1 * vv * vv));
        float sn, cn;
        sincosf(xi * u, &sn, &cn);
        v[n1] = make_float2((cn - Kr) * g * invn, (sn - Ki) * g * invn);
      }
    } else {
      const float sp = 3.2f;
      float norm = FSCALE / (TWO_PI * sp * sp);
#pragma unroll
      for (int n1 = 0; n1 < 16; ++n1) {
        int jd = 16 * n1 + t;
        float gn = (jd < 128) ? (float)jd : (float)(jd - 256);
        float g = expf(-0.5f * (gm * gm + gn * gn) / (sp * sp));
        v[n1] = make_float2(g * norm, 0.f);
      }
    }
    fft256_reg<-1, false>(v, SM + line * LSTRIDE, t);
    size_t base = ((size_t)(f * 256 + row)) << 8;
#pragma unroll
    for (int k2 = 0; k2 < 16; ++k2)
      fB[base + t + 16*k2] = v[PERM(k2)];
  } else {
    int c = threadIdx.x & 15, t = threadIdx.x >> 4;
    int bb = blockIdx.x - 144;
    int img = bb >> 4;
    size_t base = ((size_t)img << 16) + ((bb & 15) << 4) + c;
    float2 v[16];
#pragma unroll
    for (int n1 = 0; n1 < 16; ++n1)
      v[n1] = xT[base + ((size_t)(16*n1 + t) << 8)];
    fft256_reg<-1, true>(v, SM + c * LSTRIDE, t);
#pragma unroll
    for (int k2 = 0; k2 < 16; ++k2)
      Xh[base + ((size_t)(t + 16*k2) << 8)] = v[PERM(k2)];
  }
}

// Filter column FFT, writing only the REAL part (filter hats are real up to
// fp noise: Morlet = real even Gaussians in frequency).
__global__ void __launch_bounds__(256, 4) k_fcolreal(const float2* in, float* out) {
  __shared__ float2 SM[16 * LSTRIDE];
  int c = threadIdx.x & 15, t = threadIdx.x >> 4;
  int img = blockIdx.x >> 4;
  size_t base = ((size_t)img << 16) + ((blockIdx.x & 15) << 4) + c;
  float2 v[16];
#pragma unroll
  for (int n1 = 0; n1 < 16; ++n1)
    v[n1] = in[base + ((size_t)(16*n1 + t) << 8)];
  fft256_reg<-1, true>(v, SM + c * LSTRIDE, t);
#pragma unroll
  for (int k2 = 0; k2 < 16; ++k2)
    out[base + ((size_t)(t + 16*k2) << 8)] = v[PERM(k2)].x;
}

// X-stage: real-filter mul + inverse col FFT, depth-1 per block.
// grid = 8 img * 9 filters * 16 grps = 1152 blocks.
__global__ void __launch_bounds__(256, 4) k_icolmul9(const float2* Xh, const float* filt,
                                                     float2* Spsi, float2* Sphi) {
  __shared__ float2 SM[16 * LSTRIDE];
  int c = threadIdx.x & 15, t = threadIdx.x >> 4;
  int bid = blockIdx.x;
  int img = bid / 144;
  int rem = bid - img * 144;
  int f = rem >> 4;
  int grp = rem & 15;
  size_t cb = ((size_t)grp << 4) + c;
  const float2* src = Xh + ((size_t)img << 16);
  const float* ff = filt + ((size_t)f << 16);
  float2 v[16];
#pragma unroll
  for (int n1 = 0; n1 < 16; ++n1) {
    size_t a = cb + ((size_t)(16*n1 + t) << 8);
    float g = ff[a];
    float2 xh = src[a];
    v[n1] = make_float2(xh.x * g, xh.y * g);
  }
  fft256_reg<1, true>(v, SM + c * LSTRIDE, t);
  float2* dst = (f == 8) ? (Sphi + ((size_t)img << 16))
                         : (Spsi + ((size_t)(img * 8 + f) << 16));
#pragma unroll
  for (int k2 = 0; k2 < 16; ++k2)
    dst[cb + ((size_t)(t + 16*k2) << 8)] = v[PERM(k2)];
}

// U2-stage fused column kernel (monolithic, smem stash): fwd col FFT + 8x
// (real-filter-mul + inv col FFT) -> half2 mid.
__global__ void __launch_bounds__(256, 3) k_fusedcol8(const float2* in, const float* filt,
                                                      __half2* Smid) {
  __shared__ float2 SM[16 * LSTRIDE];
  __shared__ float2 SM2[16 * LSTRIDE];
  int c = threadIdx.x & 15, t = threadIdx.x >> 4;
  int img = blockIdx.x >> 4;
  size_t cb = ((blockIdx.x & 15) << 4) + c;
  size_t base = ((size_t)img << 16) + cb;
  float2* priv = SM2 + c * LSTRIDE + t * 16;
  float2 v[16];
#pragma unroll
  for (int n1 = 0; n1 < 16; ++n1)
    v[n1] = in[base + ((size_t)(16*n1 + t) << 8)];
  fft256_reg<-1, true>(v, SM + c * LSTRIDE, t);
#pragma unroll
  for (int k = 0; k < 16; ++k) priv[k] = v[PERM(k)];

  for (int f = 0; f < 8; ++f) {
    const float* ff = filt + ((size_t)f << 16);
#pragma unroll
    for (int n1 = 0; n1 < 16; ++n1) {
      float g = ff[cb + ((size_t)(t + 16*n1) << 8)];
      float2 xh = priv[n1];
      v[n1] = make_float2(xh.x * g, xh.y * g);
    }
    fft256_reg<1, true>(v, SM + c * LSTRIDE, t);
    __half2* dst = Smid + ((size_t)(img * 8 + f) << 16);
#pragma unroll
    for (int k2 = 0; k2 < 16; ++k2) {
      float2 y = v[PERM(k2)];
      dst[cb + ((size_t)(t + 16*k2) << 8)] = __floats2half2_rn(y.x, y.y);
    }
  }
}

// MERGED kernel: blocks [0,1024) = U1 rows (inv row FFT of S, abs -> out
// channel, fwd row FFT -> S2); blocks [1024,1152) = S0 rows (real -> out).
__global__ void __launch_bounds__(256, 4) k_U1S0rows(const float2* mid, float* out,
                                                     float2* S2, const float2* Sphi) {
  __shared__ float2 SM[16 * LSTRIDE];
  int t = threadIdx.x & 15, line = threadIdx.x >> 4;
  if (blockIdx.x < 1024) {
    size_t gl = (size_t)blockIdx.x * 16 + line;
    int o = (int)(gl >> 8);
    int row = (int)(gl & 255);
    size_t base = gl << 8;
    float2 v[16];
#pragma unroll
    for (int n1 = 0; n1 < 16; ++n1) v[n1] = mid[base + 16*n1 + t];
    fft256_reg<1, false>(v, SM + line * LSTRIDE, t);

    int f = o & 7, bc = o >> 3;
    int b = bc >> 1, ch = (bc & 1) * 73 + 1 + f;
    size_t obase = (((size_t)(b * 146 + ch)) << 16) + ((size_t)row << 8);
    float2 a[16];
#pragma unroll
    for (int k = 0; k < 16; ++k) {
      float2 y = v[PERM(k)];
      float m = sqrtf(y.x * y.x + y.y * y.y);
      out[obase + t + 16*k] = m;
      a[k] = make_float2(m, 0.f);   // value at index 16k+t -> input slot k
    }
    fft256_reg<-1, false>(a, SM + line * LSTRIDE, t);
#pragma unroll
    for (int k2 = 0; k2 < 16; ++k2)
      S2[base + t + 16*k2] = a[PERM(k2)];
  } else {
    size_t gl = (size_t)(blockIdx.x - 1024) * 16 + line;
    int o = (int)(gl >> 8);
    int row = (int)(gl & 255);
    size_t base = gl << 8;
    float2 v[16];
#pragma unroll
    for (int n1 = 0; n1 < 16; ++n1) v[n1] = Sphi[base + 16*n1 + t];
    fft256_reg<1, false>(v, SM + line * LSTRIDE, t);
    int b = o >> 1, ch = (o & 1) * 73;
    size_t obase = (((size_t)(b * 146 + ch)) << 16) + ((size_t)row << 8);
#pragma unroll
    for (int k2 = 0; k2 < 16; ++k2)
      out[obase + t + 16*k2] = v[PERM(k2)].x;
  }
}

// U2 final inverse row pass: abs -> out channel.
__global__ void __launch_bounds__(256, 4) k_irow_U2(const __half2* mid, float* out) {
  __shared__ float2 SM[16 * LSTRIDE];
  int t = threadIdx.x & 15, line = threadIdx.x >> 4;
  size_t gl = (size_t)blockIdx.x * 16 + line;
  int o = (int)(gl >> 8);
  int row = (int)(gl & 255);
  size_t base = gl << 8;
  float2 v[16];
#pragma unroll
  for (int n1 = 0; n1 < 16; ++n1) v[n1] = __half22float2(mid[base + 16*n1 + t]);
  fft256_reg<1, false>(v, SM + line * LSTRIDE, t);

  int f2 = o & 7, tt = o >> 3;
  int f1 = tt & 7, bc = tt >> 3;
  int b = bc >> 1, ch = (bc & 1) * 73 + 9 + f1 * 8 + f2;
  size_t obase = (((size_t)(b * 146 + ch)) << 16) + ((size_t)row << 8);
#pragma unroll
  for (int k2 = 0; k2 < 16; ++k2) {
    float2 y = v[PERM(k2)];
    out[obase + t + 16*k2] = sqrtf(y.x * y.x + y.y * y.y);
  }
}

// ---------------- launch -------------------------------------------------------
extern "C" void kernel_launch(void* const* d_in, const int* in_sizes, int n_in,
                              void* d_out, int out_size) {
  (void)in_sizes; (void)n_in; (void)out_size;
  const float* x = (const float*)d_in[0];
  const float* theta = (const float*)d_in[1];
  const float* xis = (const float*)d_in[2];
  const float* sigmas = (const float*)d_in[3];
  const float* slants = (const float*)d_in[4];
  float* out = (float*)d_out;

  void* p;
  cudaGetSymbolAddress(&p, g_fR); float*  fR = (float*)p;
  cudaGetSymbolAddress(&p, g_fB); float2* fB = (float2*)p;
  cudaGetSymbolAddress(&p, g_xT); float2* xT = (float2*)p;
  cudaGetSymbolAddress(&p, g_S2); float2* S2 = (float2*)p;
  cudaGetSymbolAddress(&p, g_S);  float2* S  = (float2*)p;
  cudaGetSymbolAddress(&p, g_Sh); __half2* Sh = (__half2*)p;
  float2* Xh = (float2*)p;   // head of g_Sh doubles as Xhat scratch (4 MB; consumed before fusedcol8)

  // Merged: filter sums (8 blks) || x row FFT (128 blks).
  k_sums_xrow<<<8 + 128, 256>>>(theta, xis, sigmas, slants, x, xT);

  // Merged: filter spatial-build + row FFT (144) || x col FFT (128).
  k_fbuild_xcol<<<144 + 128, 256>>>(theta, xis, sigmas, slants, fB, xT, Xh);

  // Filter col FFT, real part -> fR.
  k_fcolreal<<<9 * 16, 256>>>(fB, fR);

  // X-stage: 9x (real-mul + inv col FFT), depth-1.
  k_icolmul9<<<8 * 144, 256>>>(Xh, fR, S, fB);

  // Merged: U1 rows (abs -> out, fwd row FFT -> S2) || S0 rows (real -> out).
  k_U1S0rows<<<1024 + 128, 256>>>(S, out, S2, fB);

  // Fused U2 (monolithic smem-stash): fwd col FFT of S2 + 8x (real-mul + inv col FFT) -> Sh.
  k_fusedcol8<<<64 * 16, 256>>>(S2, fR, Sh);

  // U2 rows: abs -> out
  k_irow_U2<<<512 * 16, 256>>>(Sh, out);
}